// round 11
// baseline (speedup 1.0000x reference)
#include <cuda_runtime.h>
#include <cstdint>
#include <math.h>

#define BB 64
#define TT 512
#define EE 256
#define HH 256
#define KK 9
#define G4 1024              // 4*H
#define MTOT (BB*TT)         // 32768

// ---------------- scratch (device globals; no allocations allowed) ----------
__device__ float g_gx_f[(size_t)MTOT * G4];   // forward input-gate preacts (+bias)
__device__ float g_gx_b[(size_t)MTOT * G4];   // backward input-gate preacts (+bias)
__device__ float g_WtF[(size_t)HH * G4];      // W_hh_f transposed: [k][n] = [256][1024]
__device__ float g_WtB[(size_t)HH * G4];      // W_hh_b transposed
__device__ int   g_perm[BB];                  // batches sorted by length (desc)
__device__ float g_emis[(size_t)MTOT * KK];   // emissions
__device__ float g_loss[BB];                  // per-batch (num - denom)

__device__ __forceinline__ float sigf(float x)  { return 1.0f / (1.0f + __expf(-x)); }
__device__ __forceinline__ float tanhff(float x){ return 1.0f - 2.0f / (__expf(2.0f * x) + 1.0f); }

__device__ __forceinline__ unsigned int smem_u32(const void* p) {
    unsigned int a;
    asm("{ .reg .u64 t; cvta.to.shared.u64 t, %1; cvt.u32.u64 %0, t; }" : "=r"(a) : "l"(p));
    return a;
}
__device__ __forceinline__ unsigned int mapa_rank(unsigned int a, unsigned int r) {
    unsigned int d;
    asm("mapa.shared::cluster.u32 %0, %1, %2;" : "=r"(d) : "r"(a), "r"(r));
    return d;
}
__device__ __forceinline__ void st_cluster(unsigned int a, float v) {
    asm volatile("st.shared::cluster.f32 [%0], %1;" :: "r"(a), "f"(v) : "memory");
}
__device__ __forceinline__ unsigned int ctarank() {
    unsigned int r; asm("mov.u32 %0, %%cluster_ctarank;" : "=r"(r)); return r;
}
#define CLUSTER_SYNC() do { \
    asm volatile("barrier.cluster.arrive.aligned;" ::: "memory"); \
    asm volatile("barrier.cluster.wait.aligned;"   ::: "memory"); \
} while (0)

// ---------------- zero feats region --------------------------------------
__global__ void zero_kernel(float* __restrict__ p, int n) {
    int i = blockIdx.x * blockDim.x + threadIdx.x;
    if (i < n) p[i] = 0.0f;
}

// ---------------- transpose W_hh (1024x256 -> 256x1024), both dirs --------
__global__ void prep_kernel(const float* __restrict__ Whh_f,
                            const float* __restrict__ Whh_b)
{
    __shared__ float tile[32][33];
    const float* __restrict__ W  = blockIdx.z ? Whh_b : Whh_f;
    float* __restrict__       Wt = blockIdx.z ? g_WtB : g_WtF;
    const int n0 = blockIdx.x * 32;
    const int k0 = blockIdx.y * 32;
    const int tx = threadIdx.x & 31, ty = threadIdx.x >> 5;
#pragma unroll
    for (int i = 0; i < 32; i += 8)
        tile[ty + i][tx] = W[(size_t)(n0 + ty + i) * HH + k0 + tx];
    __syncthreads();
#pragma unroll
    for (int i = 0; i < 32; i += 8)
        Wt[(size_t)(k0 + ty + i) * G4 + n0 + tx] = tile[tx][ty + i];
}

// ---------------- sort batches by length (descending), odd-even ------------
__global__ void sort_kernel(const int* __restrict__ lens) {
    __shared__ int keys[BB];
    const int t = threadIdx.x;
    keys[t] = (lens[t] << 8) | t;
    for (int phase = 0; phase < BB; phase++) {
        __syncthreads();
        if ((t & 1) == (phase & 1) && t + 1 < BB) {
            int a = keys[t], b = keys[t + 1];
            if (a < b) { keys[t] = b; keys[t + 1] = a; }
        }
    }
    __syncthreads();
    g_perm[t] = keys[t] & 255;
}

// ---------------- fused embedding-gather + input GEMM ---------------------
__global__ __launch_bounds__(256, 2)
void gemm_kernel(const int* __restrict__ word_inputs,
                 const int* __restrict__ lens,
                 const float* __restrict__ word_vec,
                 const float* __restrict__ Wf, const float* __restrict__ bf,
                 const float* __restrict__ Wb, const float* __restrict__ bb)
{
    const int dir = blockIdx.z;
    const float* __restrict__ Wih  = dir ? Wb : Wf;
    const float* __restrict__ bias = dir ? bb : bf;
    float* __restrict__ gx = dir ? g_gx_b : g_gx_f;

    const int m0 = blockIdx.y * 128;
    const int n0 = blockIdx.x * 128;
    const int bidx = m0 >> 9;
    const int t0   = m0 & 511;
    if (t0 >= lens[bidx]) return;

    __shared__ float As[8][128];
    __shared__ float Bs[8][128];
    __shared__ int   sIdx[128];

    const int tid = threadIdx.x;
    if (tid < 128) sIdx[tid] = word_inputs[m0 + tid];
    __syncthreads();

    const int lr = tid >> 1;
    const int kq = (tid & 1) * 4;
    const int ty = tid >> 4, tx = tid & 15;

    const float* __restrict__ arow = word_vec + (size_t)sIdx[lr] * EE;
    const float* __restrict__ brow = Wih + (size_t)(n0 + lr) * EE;

    float acc[8][8];
#pragma unroll
    for (int i = 0; i < 8; i++)
#pragma unroll
        for (int j = 0; j < 8; j++) acc[i][j] = 0.0f;

    for (int k0 = 0; k0 < EE; k0 += 8) {
        float4 av = *(const float4*)(arow + k0 + kq);
        float4 bv = *(const float4*)(brow + k0 + kq);
        __syncthreads();
        As[kq + 0][lr] = av.x; As[kq + 1][lr] = av.y;
        As[kq + 2][lr] = av.z; As[kq + 3][lr] = av.w;
        Bs[kq + 0][lr] = bv.x; Bs[kq + 1][lr] = bv.y;
        Bs[kq + 2][lr] = bv.z; Bs[kq + 3][lr] = bv.w;
        __syncthreads();
#pragma unroll
        for (int kk = 0; kk < 8; kk++) {
            float4 a0 = *(const float4*)&As[kk][ty * 8];
            float4 a1 = *(const float4*)&As[kk][ty * 8 + 4];
            float4 b0 = *(const float4*)&Bs[kk][tx * 8];
            float4 b1 = *(const float4*)&Bs[kk][tx * 8 + 4];
            float a[8] = {a0.x, a0.y, a0.z, a0.w, a1.x, a1.y, a1.z, a1.w};
            float b[8] = {b0.x, b0.y, b0.z, b0.w, b1.x, b1.y, b1.z, b1.w};
#pragma unroll
            for (int i = 0; i < 8; i++)
#pragma unroll
                for (int j = 0; j < 8; j++)
                    acc[i][j] = fmaf(a[i], b[j], acc[i][j]);
        }
    }

    const float* bsrc = bias + n0 + tx * 8;
    float4 bb0 = *(const float4*)(bsrc);
    float4 bb1 = *(const float4*)(bsrc + 4);
    float bvals[8] = {bb0.x, bb0.y, bb0.z, bb0.w, bb1.x, bb1.y, bb1.z, bb1.w};
#pragma unroll
    for (int i = 0; i < 8; i++) {
        int m = m0 + ty * 8 + i;
        float* dst = gx + (size_t)m * G4 + n0 + tx * 8;
        float4 o0 = make_float4(acc[i][0] + bvals[0], acc[i][1] + bvals[1],
                                acc[i][2] + bvals[2], acc[i][3] + bvals[3]);
        float4 o1 = make_float4(acc[i][4] + bvals[4], acc[i][5] + bvals[5],
                                acc[i][6] + bvals[6], acc[i][7] + bvals[7]);
        *(float4*)(dst) = o0;
        *(float4*)(dst + 4) = o1;
    }
}

// ---------------- bidirectional LSTM, 8-CTA cluster, W in SMEM --------------
// grid 128 linear, cluster (8,1,1). cluster id = bx>>3: dir = cid&1, grp = cid>>1.
// Cluster handles 8 batches perm[8*grp .. +7]. Rank r owns gate columns
// [r*128, r*128+128) of the 1024, W-slice resident in SMEM (128 KB, loaded once).
// Thread t: col = t&127, bgroup g = t>>7 -> accumulates 4 batches (4g..4g+3).
// Preacts scattered to owner CTAs via DSMEM; rank r owns batch r's (c,h)
// (thread j = hidden unit j), h broadcast back to all 8 ranks' sHs[k][8].
__global__ __launch_bounds__(256, 1) __cluster_dims__(8, 1, 1)
void lstm_kernel(const int* __restrict__ lens, float* __restrict__ feats)
{
    extern __shared__ float sm[];
    float* sW   = sm;                    // [256][128]  128 KB
    float* sHs  = sm + 32768;            // [256 k][8 b] 8 KB
    float* sPre = sm + 32768 + 2048;     // [1024] preacts for MY batch
    __shared__ int sB[8], sL[8];

    const int t = threadIdx.x;
    const unsigned int rank = ctarank();
    const int cid = blockIdx.x >> 3;
    const int dir = cid & 1;
    const int grp = cid >> 1;
    const float* __restrict__ Wt = dir ? g_WtB : g_WtF;
    const float* __restrict__ gx = dir ? g_gx_b : g_gx_f;

    if (t < 8) { int b = g_perm[grp * 8 + t]; sB[t] = b; sL[t] = lens[b]; }
    // load W slice [k][128] (coalesced float4)
    for (int i = t; i < 8192; i += 256) {
        int k = i >> 5, c4 = (i & 31) << 2;
        *(float4*)&sW[k * 128 + c4] =
            *(const float4*)&Wt[(size_t)k * G4 + rank * 128 + c4];
    }
    for (int i = t; i < 2048; i += 256) sHs[i] = 0.0f;
    __syncthreads();

    const int col = t & 127, g = t >> 7;
    const int gcol = (int)rank * 128 + col;

    // precompute remote DSMEM addresses
    unsigned int preA[4], hA[8];
    unsigned int preLoc = smem_u32(&sPre[gcol]);
#pragma unroll
    for (int j = 0; j < 4; j++) preA[j] = mapa_rank(preLoc, 4 * g + j);
    unsigned int hLoc = smem_u32(&sHs[t * 8 + rank]);
#pragma unroll
    for (int r = 0; r < 8; r++) hA[r] = mapa_rank(hLoc, r);

    int Lj[4]; size_t gbase[4];
#pragma unroll
    for (int j = 0; j < 4; j++) {
        Lj[j] = sL[4 * g + j];
        gbase[j] = (size_t)sB[4 * g + j] * TT * G4 + gcol;
    }
    const int Lmax = sL[0];                  // perm sorted desc
    const int myL = sL[rank];
    const size_t fbase = (size_t)sB[rank] * TT * (2 * HH) + dir * HH + t;
    float creg = 0.0f;

    CLUSTER_SYNC();   // peers' sHs init + W load complete

    for (int s = 0; s < Lmax; s++) {
        // prefetch this step's gx (consumed after ~4K-cycle matvec)
        float gxv[4];
#pragma unroll
        for (int j = 0; j < 4; j++) {
            int tj = (s < Lj[j]) ? (dir ? Lj[j] - 1 - s : s) : 0;  // t=0 always valid
            gxv[j] = gx[gbase[j] + (size_t)tj * G4];
        }

        float a0 = 0, a1 = 0, a2 = 0, a3 = 0;
        const float* __restrict__ hb = sHs + 4 * g;   // warp-uniform
#pragma unroll 8
        for (int k = 0; k < 256; k++) {
            float w = sW[k * 128 + col];
            float4 h4 = *(const float4*)&hb[k * 8];
            a0 = fmaf(w, h4.x, a0); a1 = fmaf(w, h4.y, a1);
            a2 = fmaf(w, h4.z, a2); a3 = fmaf(w, h4.w, a3);
        }
        st_cluster(preA[0], a0 + gxv[0]);
        st_cluster(preA[1], a1 + gxv[1]);
        st_cluster(preA[2], a2 + gxv[2]);
        st_cluster(preA[3], a3 + gxv[3]);
        CLUSTER_SYNC();   // preacts delivered to owner CTAs

        if (s < myL) {
            float iv = sPre[t], fv = sPre[256 + t], gv = sPre[512 + t], ov = sPre[768 + t];
            creg = fmaf(sigf(fv), creg, sigf(iv) * tanhff(gv));
            float hv = sigf(ov) * tanhff(creg);
#pragma unroll
            for (int r = 0; r < 8; r++) st_cluster(hA[r], hv);   // broadcast h
            int tc = dir ? (myL - 1 - s) : s;
            feats[fbase + (size_t)tc * (2 * HH)] = hv;
        }
        CLUSTER_SYNC();   // new h visible everywhere
    }
}

// ---------------- emissions: feats @ W_out^T + b_out ----------------------
__global__ void emis_kernel(const float* __restrict__ feats,
                            const float* __restrict__ Wout,
                            const float* __restrict__ bout)
{
    __shared__ float sW[KK][2 * HH];
    const int tid = threadIdx.x;
    for (int i = tid; i < KK * 2 * HH; i += 256)
        sW[i / (2 * HH)][i % (2 * HH)] = Wout[i];
    __syncthreads();

    const int warp = tid >> 5, lane = tid & 31;
    const int row = blockIdx.x * 8 + warp;
    const float* __restrict__ fr = feats + (size_t)row * (2 * HH);
    float acc[KK];
#pragma unroll
    for (int k = 0; k < KK; k++) acc[k] = 0.0f;
#pragma unroll 4
    for (int it = 0; it < 16; it++) {
        float x = fr[it * 32 + lane];
#pragma unroll
        for (int k = 0; k < KK; k++) acc[k] = fmaf(x, sW[k][it * 32 + lane], acc[k]);
    }
#pragma unroll
    for (int k = 0; k < KK; k++) {
        float v = acc[k];
#pragma unroll
        for (int off = 16; off; off >>= 1) v += __shfl_xor_sync(0xffffffffu, v, off);
        if (lane == 0) g_emis[(size_t)row * KK + k] = v + bout[k];
    }
}

// ---------------- CRF: alpha + numerator (warp0), viterbi + preds (warp1) --
__global__ void crf_kernel(const int* __restrict__ lens, const int* __restrict__ labels,
                           const float* __restrict__ start_t, const float* __restrict__ end_t,
                           const float* __restrict__ trans, float* __restrict__ preds_out)
{
    const int b = blockIdx.x;
    const int L = lens[b];
    const int tid = threadIdx.x, warp = tid >> 5, lane = tid & 31;
    const float* __restrict__ em = g_emis + (size_t)b * TT * KK;
    __shared__ unsigned char hist[TT][KK];

    const float NEG = -1e30f;
    const int j = lane;
    float tr[KK];
#pragma unroll
    for (int i = 0; i < KK; i++) tr[i] = (j < KK) ? trans[i * KK + j] : 0.0f;

    if (warp == 0) {
        float score = (j < KK) ? (start_t[j] + em[j]) : NEG;
        for (int t = 1; t < L; t++) {
            float v[KK], mx = NEG;
#pragma unroll
            for (int i = 0; i < KK; i++) {
                v[i] = __shfl_sync(0xffffffffu, score, i) + tr[i];
                mx = fmaxf(mx, v[i]);
            }
            float sum = 0.0f;
#pragma unroll
            for (int i = 0; i < KK; i++) sum += __expf(v[i] - mx);
            float e = (j < KK) ? em[t * KK + j] : 0.0f;
            float nxt = mx + __logf(sum) + e;
            if (j < KK) score = nxt;
        }
        float z = (j < KK) ? (score + end_t[j]) : NEG;
        float mz = z;
#pragma unroll
        for (int off = 16; off; off >>= 1) mz = fmaxf(mz, __shfl_xor_sync(0xffffffffu, mz, off));
        float se = (j < KK) ? __expf(z - mz) : 0.0f;
#pragma unroll
        for (int off = 16; off; off >>= 1) se += __shfl_xor_sync(0xffffffffu, se, off);
        float denom = mz + __logf(se);

        const int* __restrict__ lab = labels + b * TT;
        float acc = 0.0f;
        for (int t = 1 + lane; t < L; t += 32) {
            int yp = lab[t - 1], y = lab[t];
            acc += trans[yp * KK + y] + em[t * KK + y];
        }
#pragma unroll
        for (int off = 16; off; off >>= 1) acc += __shfl_xor_sync(0xffffffffu, acc, off);
        if (lane == 0) {
            int y0 = lab[0], yl = lab[L - 1];
            float num = acc + start_t[y0] + em[y0] + end_t[yl];
            g_loss[b] = num - denom;
        }
    } else {
        float score = (j < KK) ? (start_t[j] + em[j]) : NEG;
        for (int t = 1; t < L; t++) {
            float best = NEG; int barg = 0;
#pragma unroll
            for (int i = 0; i < KK; i++) {
                float v = __shfl_sync(0xffffffffu, score, i) + tr[i];
                if (v > best) { best = v; barg = i; }
            }
            if (j < KK) {
                hist[t - 1][j] = (unsigned char)barg;
                score = best + em[t * KK + j];
            }
        }
        float z = (j < KK) ? (score + end_t[j]) : NEG;
        int idx = j;
#pragma unroll
        for (int off = 16; off; off >>= 1) {
            float oz = __shfl_xor_sync(0xffffffffu, z, off);
            int   oi = __shfl_xor_sync(0xffffffffu, idx, off);
            if (oz > z || (oz == z && oi < idx)) { z = oz; idx = oi; }
        }
        int best_last = __shfl_sync(0xffffffffu, idx, 0);

        float* __restrict__ po = preds_out + (size_t)b * TT;
        for (int t = L + lane; t < TT; t += 32) po[t] = 0.0f;
        if (lane == 0) {
            int cur = best_last;
            po[L - 1] = (float)cur;
            for (int t = L - 2; t >= 0; t--) { cur = hist[t][cur]; po[t] = (float)cur; }
        }
    }
}

// ---------------- deterministic loss reduction ----------------------------
__global__ void finalize_kernel(float* __restrict__ out) {
    if (threadIdx.x == 0) {
        float s = 0.0f;
        for (int i = 0; i < BB; i++) s += g_loss[i];
        out[0] = -s / (float)BB;
    }
}

// ---------------- launch ---------------------------------------------------
extern "C" void kernel_launch(void* const* d_in, const int* in_sizes, int n_in,
                              void* d_out, int out_size) {
    const int*   wi    = (const int*)d_in[0];
    const int*   lens  = (const int*)d_in[1];
    const int*   lab   = (const int*)d_in[2];
    const float* wv    = (const float*)d_in[3];
    const float* Wihf  = (const float*)d_in[4];
    const float* Whhf  = (const float*)d_in[5];
    const float* bf    = (const float*)d_in[6];
    const float* Wihb  = (const float*)d_in[7];
    const float* Whhb  = (const float*)d_in[8];
    const float* bb    = (const float*)d_in[9];
    const float* Wout  = (const float*)d_in[10];
    const float* bout  = (const float*)d_in[11];
    const float* st    = (const float*)d_in[12];
    const float* en    = (const float*)d_in[13];
    const float* tr    = (const float*)d_in[14];

    float* out       = (float*)d_out;
    float* preds_out = out + 1;
    float* feats     = out + 1 + BB * TT;

    const int lstm_smem = (32768 + 2048 + 1024) * 4;   // 143360 B
    cudaFuncSetAttribute(lstm_kernel,
                         cudaFuncAttributeMaxDynamicSharedMemorySize, lstm_smem);

    const int nfeat = MTOT * 2 * HH;
    zero_kernel<<<(nfeat + 255) / 256, 256>>>(feats, nfeat);
    prep_kernel<<<dim3(G4 / 32, HH / 32, 2), 256>>>(Whhf, Whhb);
    sort_kernel<<<1, BB>>>(lens);
    gemm_kernel<<<dim3(G4 / 128, MTOT / 128, 2), 256>>>(wi, lens, wv, Wihf, bf, Wihb, bb);
    lstm_kernel<<<128, 256, lstm_smem>>>(lens, feats);
    emis_kernel<<<MTOT / 8, 256>>>(feats, Wout, bout);
    crf_kernel<<<BB, 64>>>(lens, lab, st, en, tr, preds_out);
    finalize_kernel<<<1, 32>>>(out);
}

// round 12
// speedup vs baseline: 1.8237x; 1.8237x over previous
#include <cuda_runtime.h>
#include <cuda_fp16.h>
#include <cstdint>
#include <math.h>

#define BB 64
#define TT 512
#define EE 256
#define HH 256
#define KK 9
#define G4 1024              // 4*H
#define MTOT (BB*TT)         // 32768

// ---------------- scratch (device globals; no allocations allowed) ----------
__device__ float   g_gx_f[(size_t)MTOT * G4];  // forward input-gate preacts (+bias)
__device__ float   g_gx_b[(size_t)MTOT * G4];  // backward input-gate preacts (+bias)
__device__ __half2 g_WhF[(size_t)128 * G4];    // W_hh_f fp16, [k/2][1024] (lo=even k)
__device__ __half2 g_WhB[(size_t)128 * G4];    // W_hh_b fp16
__device__ int     g_perm[BB];                 // batches sorted by length (desc)
__device__ float   g_emis[(size_t)MTOT * KK];  // emissions
__device__ float   g_loss[BB];                 // per-batch (num - denom)

__device__ __forceinline__ float sigf(float x)  { return 1.0f / (1.0f + __expf(-x)); }
__device__ __forceinline__ float tanhff(float x){ return 1.0f - 2.0f / (__expf(2.0f * x) + 1.0f); }

__device__ __forceinline__ unsigned int smem_u32(const void* p) {
    unsigned int a;
    asm("{ .reg .u64 t; cvta.to.shared.u64 t, %1; cvt.u32.u64 %0, t; }" : "=r"(a) : "l"(p));
    return a;
}
__device__ __forceinline__ unsigned int mapa_rank(unsigned int a, unsigned int r) {
    unsigned int d;
    asm("mapa.shared::cluster.u32 %0, %1, %2;" : "=r"(d) : "r"(a), "r"(r));
    return d;
}
__device__ __forceinline__ void st_cluster(unsigned int a, float v) {
    asm volatile("st.shared::cluster.f32 [%0], %1;" :: "r"(a), "f"(v) : "memory");
}
__device__ __forceinline__ unsigned int ctarank() {
    unsigned int r; asm("mov.u32 %0, %%cluster_ctarank;" : "=r"(r)); return r;
}
#define CLUSTER_SYNC() do { \
    asm volatile("barrier.cluster.arrive.aligned;" ::: "memory"); \
    asm volatile("barrier.cluster.wait.aligned;"   ::: "memory"); \
} while (0)

// ---------------- zero feats region --------------------------------------
__global__ void zero_kernel(float* __restrict__ p, int n) {
    int i = blockIdx.x * blockDim.x + threadIdx.x;
    if (i < n) p[i] = 0.0f;
}

// ---- transpose+convert W_hh (1024x256 fp32 -> [k/2][1024] half2), both dirs
__global__ void prep_kernel(const float* __restrict__ Whh_f,
                            const float* __restrict__ Whh_b)
{
    __shared__ float tile[32][33];                 // [n][k]
    const float* __restrict__ W  = blockIdx.z ? Whh_b : Whh_f;
    __half2* __restrict__     Wh = blockIdx.z ? g_WhB : g_WhF;
    const int n0 = blockIdx.x * 32;   // gate row 0..1023
    const int k0 = blockIdx.y * 32;   // k 0..255
    const int tx = threadIdx.x & 31, ty = threadIdx.x >> 5;  // 32x8
#pragma unroll
    for (int i = 0; i < 32; i += 8)
        tile[ty + i][tx] = W[(size_t)(n0 + ty + i) * HH + k0 + tx];
    __syncthreads();
#pragma unroll
    for (int i = 0; i < 16; i += 8) {
        int k2 = ty + i;              // 0..15 local
        __half2 v = __floats2half2_rn(tile[tx][2 * k2], tile[tx][2 * k2 + 1]);
        Wh[(size_t)(k0 / 2 + k2) * G4 + n0 + tx] = v;
    }
}

// ---------------- sort batches by length (descending), odd-even ------------
__global__ void sort_kernel(const int* __restrict__ lens) {
    __shared__ int keys[BB];
    const int t = threadIdx.x;
    keys[t] = (lens[t] << 8) | t;
    for (int phase = 0; phase < BB; phase++) {
        __syncthreads();
        if ((t & 1) == (phase & 1) && t + 1 < BB) {
            int a = keys[t], b = keys[t + 1];
            if (a < b) { keys[t] = b; keys[t + 1] = a; }
        }
    }
    __syncthreads();
    g_perm[t] = keys[t] & 255;
}

// ---------------- fused embedding-gather + input GEMM ---------------------
__global__ __launch_bounds__(256, 2)
void gemm_kernel(const int* __restrict__ word_inputs,
                 const int* __restrict__ lens,
                 const float* __restrict__ word_vec,
                 const float* __restrict__ Wf, const float* __restrict__ bf,
                 const float* __restrict__ Wb, const float* __restrict__ bb)
{
    const int dir = blockIdx.z;
    const float* __restrict__ Wih  = dir ? Wb : Wf;
    const float* __restrict__ bias = dir ? bb : bf;
    float* __restrict__ gx = dir ? g_gx_b : g_gx_f;

    const int m0 = blockIdx.y * 128;
    const int n0 = blockIdx.x * 128;
    const int bidx = m0 >> 9;
    const int t0   = m0 & 511;
    if (t0 >= lens[bidx]) return;

    __shared__ float As[8][128];
    __shared__ float Bs[8][128];
    __shared__ int   sIdx[128];

    const int tid = threadIdx.x;
    if (tid < 128) sIdx[tid] = word_inputs[m0 + tid];
    __syncthreads();

    const int lr = tid >> 1;
    const int kq = (tid & 1) * 4;
    const int ty = tid >> 4, tx = tid & 15;

    const float* __restrict__ arow = word_vec + (size_t)sIdx[lr] * EE;
    const float* __restrict__ brow = Wih + (size_t)(n0 + lr) * EE;

    float acc[8][8];
#pragma unroll
    for (int i = 0; i < 8; i++)
#pragma unroll
        for (int j = 0; j < 8; j++) acc[i][j] = 0.0f;

    for (int k0 = 0; k0 < EE; k0 += 8) {
        float4 av = *(const float4*)(arow + k0 + kq);
        float4 bv = *(const float4*)(brow + k0 + kq);
        __syncthreads();
        As[kq + 0][lr] = av.x; As[kq + 1][lr] = av.y;
        As[kq + 2][lr] = av.z; As[kq + 3][lr] = av.w;
        Bs[kq + 0][lr] = bv.x; Bs[kq + 1][lr] = bv.y;
        Bs[kq + 2][lr] = bv.z; Bs[kq + 3][lr] = bv.w;
        __syncthreads();
#pragma unroll
        for (int kk = 0; kk < 8; kk++) {
            float4 a0 = *(const float4*)&As[kk][ty * 8];
            float4 a1 = *(const float4*)&As[kk][ty * 8 + 4];
            float4 b0 = *(const float4*)&Bs[kk][tx * 8];
            float4 b1 = *(const float4*)&Bs[kk][tx * 8 + 4];
            float a[8] = {a0.x, a0.y, a0.z, a0.w, a1.x, a1.y, a1.z, a1.w};
            float b[8] = {b0.x, b0.y, b0.z, b0.w, b1.x, b1.y, b1.z, b1.w};
#pragma unroll
            for (int i = 0; i < 8; i++)
#pragma unroll
                for (int j = 0; j < 8; j++)
                    acc[i][j] = fmaf(a[i], b[j], acc[i][j]);
        }
    }

    const float* bsrc = bias + n0 + tx * 8;
    float4 bb0 = *(const float4*)(bsrc);
    float4 bb1 = *(const float4*)(bsrc + 4);
    float bvals[8] = {bb0.x, bb0.y, bb0.z, bb0.w, bb1.x, bb1.y, bb1.z, bb1.w};
#pragma unroll
    for (int i = 0; i < 8; i++) {
        int m = m0 + ty * 8 + i;
        float* dst = gx + (size_t)m * G4 + n0 + tx * 8;
        float4 o0 = make_float4(acc[i][0] + bvals[0], acc[i][1] + bvals[1],
                                acc[i][2] + bvals[2], acc[i][3] + bvals[3]);
        float4 o1 = make_float4(acc[i][4] + bvals[4], acc[i][5] + bvals[5],
                                acc[i][6] + bvals[6], acc[i][7] + bvals[7]);
        *(float4*)(dst) = o0;
        *(float4*)(dst + 4) = o1;
    }
}

// ---------------- bidirectional LSTM, 2-CTA cluster, fp16 W, 1 sync/step ----
// grid (32, 2, 2), cluster (1,1,2). rank r owns gate cols [r*512, r*512+512).
// Thread t owns ONE column gcol = r*512+t for BOTH batches; loads k-packed
// half2 W. Preacts pushed to BOTH CTAs' pre[s&1] buffers (local store + one
// DSMEM store per batch); single cluster.sync; then both CTAs redundantly
// compute activations/c/h for both batches (identical, deterministic).
__global__ __launch_bounds__(512, 1) __cluster_dims__(1, 1, 2)
void lstm_kernel(const int* __restrict__ lens, float* __restrict__ feats)
{
    const int dir = blockIdx.y;
    const __half2* __restrict__ Wp = dir ? g_WhB : g_WhF;   // [k2][1024]
    const float* __restrict__ gx   = dir ? g_gx_b : g_gx_f;
    const int b0 = g_perm[2 * blockIdx.x];
    const int b1 = g_perm[2 * blockIdx.x + 1];
    const int L0 = lens[b0], L1 = lens[b1];   // sorted: L0 >= L1
    const unsigned int rank = ctarank();

    __shared__ __align__(16) float hs[2][HH];      // h, both batches
    __shared__ float pre[2][2][G4];                // [buf][batch][gate]  16 KB

    const int t = threadIdx.x;
    if (t < HH) { hs[0][t] = 0.0f; hs[1][t] = 0.0f; }

    const int gcol = (int)rank * 512 + t;
    unsigned int remo[2][2];
#pragma unroll
    for (int bf = 0; bf < 2; bf++) {
        remo[bf][0] = mapa_rank(smem_u32(&pre[bf][0][gcol]), rank ^ 1);
        remo[bf][1] = mapa_rank(smem_u32(&pre[bf][1][gcol]), rank ^ 1);
    }
    const __half2* __restrict__ wcol = Wp + gcol;
    const int b = t >> 8, j = t & 255;
    const size_t gb0 = (size_t)b0 * TT * G4 + gcol;
    const size_t gb1 = (size_t)b1 * TT * G4 + gcol;
    const int bb = b ? b1 : b0;
    float creg = 0.0f;

    CLUSTER_SYNC();

    for (int s = 0; s < L0; s++) {
        const bool act1 = s < L1;
        const int t0 = dir ? (L0 - 1 - s) : s;
        const int t1 = act1 ? (dir ? (L1 - 1 - s) : s) : 0;
        // prefetch gx (consumed after the ~5K-cycle matvec)
        float gv0 = gx[gb0 + (size_t)t0 * G4];
        float gv1 = gx[gb1 + (size_t)t1 * G4];

        float a0 = 0.0f, a1 = 0.0f;
        const float2* __restrict__ h0p = (const float2*)hs[0];
        const float2* __restrict__ h1p = (const float2*)hs[1];
#pragma unroll 8
        for (int k2 = 0; k2 < 128; k2++) {
            float2 wf = __half22float2(wcol[(size_t)k2 * G4]);
            float2 h0 = h0p[k2], h1 = h1p[k2];
            a0 = fmaf(wf.x, h0.x, a0); a0 = fmaf(wf.y, h0.y, a0);
            a1 = fmaf(wf.x, h1.x, a1); a1 = fmaf(wf.y, h1.y, a1);
        }
        const int bf = s & 1;
        float p0 = a0 + gv0, p1 = a1 + gv1;
        pre[bf][0][gcol] = p0;
        pre[bf][1][gcol] = p1;
        st_cluster(remo[bf][0], p0);
        st_cluster(remo[bf][1], p1);
        CLUSTER_SYNC();   // full preacts visible in both CTAs

        if (b == 0 || act1) {
            float iv = pre[bf][b][j],       fv = pre[bf][b][j + 256];
            float gg = pre[bf][b][j + 512], ov = pre[bf][b][j + 768];
            creg = fmaf(sigf(fv), creg, sigf(iv) * tanhff(gg));
            float hv = sigf(ov) * tanhff(creg);
            hs[b][j] = hv;
            if ((int)rank == b) {
                int tc = b ? t1 : t0;
                feats[(size_t)(bb * TT + tc) * (2 * HH) + dir * HH + j] = hv;
            }
        }
        __syncthreads();   // hs updates visible to next matvec (intra-CTA)
    }
}

// ---------------- emissions: feats @ W_out^T + b_out ----------------------
__global__ void emis_kernel(const float* __restrict__ feats,
                            const float* __restrict__ Wout,
                            const float* __restrict__ bout)
{
    __shared__ float sW[KK][2 * HH];
    const int tid = threadIdx.x;
    for (int i = tid; i < KK * 2 * HH; i += 256)
        sW[i / (2 * HH)][i % (2 * HH)] = Wout[i];
    __syncthreads();

    const int warp = tid >> 5, lane = tid & 31;
    const int row = blockIdx.x * 8 + warp;
    const float* __restrict__ fr = feats + (size_t)row * (2 * HH);
    float acc[KK];
#pragma unroll
    for (int k = 0; k < KK; k++) acc[k] = 0.0f;
#pragma unroll 4
    for (int it = 0; it < 16; it++) {
        float x = fr[it * 32 + lane];
#pragma unroll
        for (int k = 0; k < KK; k++) acc[k] = fmaf(x, sW[k][it * 32 + lane], acc[k]);
    }
#pragma unroll
    for (int k = 0; k < KK; k++) {
        float v = acc[k];
#pragma unroll
        for (int off = 16; off; off >>= 1) v += __shfl_xor_sync(0xffffffffu, v, off);
        if (lane == 0) g_emis[(size_t)row * KK + k] = v + bout[k];
    }
}

// ---------------- CRF: alpha + numerator (warp0), viterbi + preds (warp1) --
__global__ void crf_kernel(const int* __restrict__ lens, const int* __restrict__ labels,
                           const float* __restrict__ start_t, const float* __restrict__ end_t,
                           const float* __restrict__ trans, float* __restrict__ preds_out)
{
    const int b = blockIdx.x;
    const int L = lens[b];
    const int tid = threadIdx.x, warp = tid >> 5, lane = tid & 31;
    const float* __restrict__ em = g_emis + (size_t)b * TT * KK;
    __shared__ unsigned char hist[TT][KK];

    const float NEG = -1e30f;
    const int j = lane;
    float tr[KK];
#pragma unroll
    for (int i = 0; i < KK; i++) tr[i] = (j < KK) ? trans[i * KK + j] : 0.0f;

    if (warp == 0) {
        float score = (j < KK) ? (start_t[j] + em[j]) : NEG;
        for (int t = 1; t < L; t++) {
            float v[KK], mx = NEG;
#pragma unroll
            for (int i = 0; i < KK; i++) {
                v[i] = __shfl_sync(0xffffffffu, score, i) + tr[i];
                mx = fmaxf(mx, v[i]);
            }
            float sum = 0.0f;
#pragma unroll
            for (int i = 0; i < KK; i++) sum += __expf(v[i] - mx);
            float e = (j < KK) ? em[t * KK + j] : 0.0f;
            float nxt = mx + __logf(sum) + e;
            if (j < KK) score = nxt;
        }
        float z = (j < KK) ? (score + end_t[j]) : NEG;
        float mz = z;
#pragma unroll
        for (int off = 16; off; off >>= 1) mz = fmaxf(mz, __shfl_xor_sync(0xffffffffu, mz, off));
        float se = (j < KK) ? __expf(z - mz) : 0.0f;
#pragma unroll
        for (int off = 16; off; off >>= 1) se += __shfl_xor_sync(0xffffffffu, se, off);
        float denom = mz + __logf(se);

        const int* __restrict__ lab = labels + b * TT;
        float acc = 0.0f;
        for (int t = 1 + lane; t < L; t += 32) {
            int yp = lab[t - 1], y = lab[t];
            acc += trans[yp * KK + y] + em[t * KK + y];
        }
#pragma unroll
        for (int off = 16; off; off >>= 1) acc += __shfl_xor_sync(0xffffffffu, acc, off);
        if (lane == 0) {
            int y0 = lab[0], yl = lab[L - 1];
            float num = acc + start_t[y0] + em[y0] + end_t[yl];
            g_loss[b] = num - denom;
        }
    } else {
        float score = (j < KK) ? (start_t[j] + em[j]) : NEG;
        for (int t = 1; t < L; t++) {
            float best = NEG; int barg = 0;
#pragma unroll
            for (int i = 0; i < KK; i++) {
                float v = __shfl_sync(0xffffffffu, score, i) + tr[i];
                if (v > best) { best = v; barg = i; }
            }
            if (j < KK) {
                hist[t - 1][j] = (unsigned char)barg;
                score = best + em[t * KK + j];
            }
        }
        float z = (j < KK) ? (score + end_t[j]) : NEG;
        int idx = j;
#pragma unroll
        for (int off = 16; off; off >>= 1) {
            float oz = __shfl_xor_sync(0xffffffffu, z, off);
            int   oi = __shfl_xor_sync(0xffffffffu, idx, off);
            if (oz > z || (oz == z && oi < idx)) { z = oz; idx = oi; }
        }
        int best_last = __shfl_sync(0xffffffffu, idx, 0);

        float* __restrict__ po = preds_out + (size_t)b * TT;
        for (int t = L + lane; t < TT; t += 32) po[t] = 0.0f;
        if (lane == 0) {
            int cur = best_last;
            po[L - 1] = (float)cur;
            for (int t = L - 2; t >= 0; t--) { cur = hist[t][cur]; po[t] = (float)cur; }
        }
    }
}

// ---------------- deterministic loss reduction ----------------------------
__global__ void finalize_kernel(float* __restrict__ out) {
    if (threadIdx.x == 0) {
        float s = 0.0f;
        for (int i = 0; i < BB; i++) s += g_loss[i];
        out[0] = -s / (float)BB;
    }
}

// ---------------- launch ---------------------------------------------------
extern "C" void kernel_launch(void* const* d_in, const int* in_sizes, int n_in,
                              void* d_out, int out_size) {
    const int*   wi    = (const int*)d_in[0];
    const int*   lens  = (const int*)d_in[1];
    const int*   lab   = (const int*)d_in[2];
    const float* wv    = (const float*)d_in[3];
    const float* Wihf  = (const float*)d_in[4];
    const float* Whhf  = (const float*)d_in[5];
    const float* bf    = (const float*)d_in[6];
    const float* Wihb  = (const float*)d_in[7];
    const float* Whhb  = (const float*)d_in[8];
    const float* bb    = (const float*)d_in[9];
    const float* Wout  = (const float*)d_in[10];
    const float* bout  = (const float*)d_in[11];
    const float* st    = (const float*)d_in[12];
    const float* en    = (const float*)d_in[13];
    const float* tr    = (const float*)d_in[14];

    float* out       = (float*)d_out;
    float* preds_out = out + 1;
    float* feats     = out + 1 + BB * TT;

    const int nfeat = MTOT * 2 * HH;
    zero_kernel<<<(nfeat + 255) / 256, 256>>>(feats, nfeat);
    prep_kernel<<<dim3(32, 8, 2), 256>>>(Whhf, Whhb);
    sort_kernel<<<1, BB>>>(lens);
    gemm_kernel<<<dim3(G4 / 128, MTOT / 128, 2), 256>>>(wi, lens, wv, Wihf, bf, Wihb, bb);
    lstm_kernel<<<dim3(BB / 2, 2, 2), 512>>>(lens, feats);
    emis_kernel<<<MTOT / 8, 256>>>(feats, Wout, bout);
    crf_kernel<<<BB, 64>>>(lens, lab, st, en, tr, preds_out);
    finalize_kernel<<<1, 32>>>(out);
}

// round 13
// speedup vs baseline: 1.8277x; 1.0022x over previous
#include <cuda_runtime.h>
#include <cuda_fp16.h>
#include <cstdint>
#include <math.h>

#define BB 64
#define TT 512
#define EE 256
#define HH 256
#define KK 9
#define G4 1024              // 4*H
#define MTOT (BB*TT)         // 32768

// ---------------- scratch (device globals; no allocations allowed) ----------
__device__ float   g_gx_f[(size_t)MTOT * G4];  // forward input-gate preacts (+bias)
__device__ float   g_gx_b[(size_t)MTOT * G4];  // backward input-gate preacts (+bias)
__device__ __half2 g_WhF[(size_t)128 * G4];    // W_hh_f fp16, [k/2][1024] (lo=even k)
__device__ __half2 g_WhB[(size_t)128 * G4];    // W_hh_b fp16
__device__ int     g_perm[BB];                 // batches sorted by length (desc)
__device__ float   g_emis[(size_t)MTOT * KK];  // emissions
__device__ float   g_loss[BB];                 // per-batch (num - denom)

__device__ __forceinline__ float sigf(float x)  { return 1.0f / (1.0f + __expf(-x)); }
__device__ __forceinline__ float tanhff(float x){ return 1.0f - 2.0f / (__expf(2.0f * x) + 1.0f); }

__device__ __forceinline__ unsigned int smem_u32(const void* p) {
    unsigned int a;
    asm("{ .reg .u64 t; cvta.to.shared.u64 t, %1; cvt.u32.u64 %0, t; }" : "=r"(a) : "l"(p));
    return a;
}
__device__ __forceinline__ unsigned int mapa_rank(unsigned int a, unsigned int r) {
    unsigned int d;
    asm("mapa.shared::cluster.u32 %0, %1, %2;" : "=r"(d) : "r"(a), "r"(r));
    return d;
}
__device__ __forceinline__ void st_cluster2(unsigned int a, float x, float y) {
    asm volatile("st.shared::cluster.v2.f32 [%0], {%1, %2};"
                 :: "r"(a), "f"(x), "f"(y) : "memory");
}
__device__ __forceinline__ unsigned int ctarank() {
    unsigned int r; asm("mov.u32 %0, %%cluster_ctarank;" : "=r"(r)); return r;
}
#define CLUSTER_SYNC() do { \
    asm volatile("barrier.cluster.arrive.aligned;" ::: "memory"); \
    asm volatile("barrier.cluster.wait.aligned;"   ::: "memory"); \
} while (0)

// ---------------- zero feats region --------------------------------------
__global__ void zero_kernel(float* __restrict__ p, int n) {
    int i = blockIdx.x * blockDim.x + threadIdx.x;
    if (i < n) p[i] = 0.0f;
}

// ---- transpose+convert W_hh (1024x256 fp32 -> [k/2][1024] half2), both dirs
__global__ void prep_kernel(const float* __restrict__ Whh_f,
                            const float* __restrict__ Whh_b)
{
    __shared__ float tile[32][33];                 // [n][k]
    const float* __restrict__ W  = blockIdx.z ? Whh_b : Whh_f;
    __half2* __restrict__     Wh = blockIdx.z ? g_WhB : g_WhF;
    const int n0 = blockIdx.x * 32;   // gate row 0..1023
    const int k0 = blockIdx.y * 32;   // k 0..255
    const int tx = threadIdx.x & 31, ty = threadIdx.x >> 5;  // 32x8
#pragma unroll
    for (int i = 0; i < 32; i += 8)
        tile[ty + i][tx] = W[(size_t)(n0 + ty + i) * HH + k0 + tx];
    __syncthreads();
#pragma unroll
    for (int i = 0; i < 16; i += 8) {
        int k2 = ty + i;              // 0..15 local
        __half2 v = __floats2half2_rn(tile[tx][2 * k2], tile[tx][2 * k2 + 1]);
        Wh[(size_t)(k0 / 2 + k2) * G4 + n0 + tx] = v;
    }
}

// ---------------- sort batches by length (descending), odd-even ------------
__global__ void sort_kernel(const int* __restrict__ lens) {
    __shared__ int keys[BB];
    const int t = threadIdx.x;
    keys[t] = (lens[t] << 8) | t;
    for (int phase = 0; phase < BB; phase++) {
        __syncthreads();
        if ((t & 1) == (phase & 1) && t + 1 < BB) {
            int a = keys[t], b = keys[t + 1];
            if (a < b) { keys[t] = b; keys[t + 1] = a; }
        }
    }
    __syncthreads();
    g_perm[t] = keys[t] & 255;
}

// ---------------- fused embedding-gather + input GEMM ---------------------
__global__ __launch_bounds__(256, 2)
void gemm_kernel(const int* __restrict__ word_inputs,
                 const int* __restrict__ lens,
                 const float* __restrict__ word_vec,
                 const float* __restrict__ Wf, const float* __restrict__ bf,
                 const float* __restrict__ Wb, const float* __restrict__ bb)
{
    const int dir = blockIdx.z;
    const float* __restrict__ Wih  = dir ? Wb : Wf;
    const float* __restrict__ bias = dir ? bb : bf;
    float* __restrict__ gx = dir ? g_gx_b : g_gx_f;

    const int m0 = blockIdx.y * 128;
    const int n0 = blockIdx.x * 128;
    const int bidx = m0 >> 9;
    const int t0   = m0 & 511;
    if (t0 >= lens[bidx]) return;

    __shared__ float As[8][128];
    __shared__ float Bs[8][128];
    __shared__ int   sIdx[128];

    const int tid = threadIdx.x;
    if (tid < 128) sIdx[tid] = word_inputs[m0 + tid];
    __syncthreads();

    const int lr = tid >> 1;
    const int kq = (tid & 1) * 4;
    const int ty = tid >> 4, tx = tid & 15;

    const float* __restrict__ arow = word_vec + (size_t)sIdx[lr] * EE;
    const float* __restrict__ brow = Wih + (size_t)(n0 + lr) * EE;

    float acc[8][8];
#pragma unroll
    for (int i = 0; i < 8; i++)
#pragma unroll
        for (int j = 0; j < 8; j++) acc[i][j] = 0.0f;

    for (int k0 = 0; k0 < EE; k0 += 8) {
        float4 av = *(const float4*)(arow + k0 + kq);
        float4 bv = *(const float4*)(brow + k0 + kq);
        __syncthreads();
        As[kq + 0][lr] = av.x; As[kq + 1][lr] = av.y;
        As[kq + 2][lr] = av.z; As[kq + 3][lr] = av.w;
        Bs[kq + 0][lr] = bv.x; Bs[kq + 1][lr] = bv.y;
        Bs[kq + 2][lr] = bv.z; Bs[kq + 3][lr] = bv.w;
        __syncthreads();
#pragma unroll
        for (int kk = 0; kk < 8; kk++) {
            float4 a0 = *(const float4*)&As[kk][ty * 8];
            float4 a1 = *(const float4*)&As[kk][ty * 8 + 4];
            float4 b0 = *(const float4*)&Bs[kk][tx * 8];
            float4 b1 = *(const float4*)&Bs[kk][tx * 8 + 4];
            float a[8] = {a0.x, a0.y, a0.z, a0.w, a1.x, a1.y, a1.z, a1.w};
            float b[8] = {b0.x, b0.y, b0.z, b0.w, b1.x, b1.y, b1.z, b1.w};
#pragma unroll
            for (int i = 0; i < 8; i++)
#pragma unroll
                for (int j = 0; j < 8; j++)
                    acc[i][j] = fmaf(a[i], b[j], acc[i][j]);
        }
    }

    const float* bsrc = bias + n0 + tx * 8;
    float4 bb0 = *(const float4*)(bsrc);
    float4 bb1 = *(const float4*)(bsrc + 4);
    float bvals[8] = {bb0.x, bb0.y, bb0.z, bb0.w, bb1.x, bb1.y, bb1.z, bb1.w};
#pragma unroll
    for (int i = 0; i < 8; i++) {
        int m = m0 + ty * 8 + i;
        float* dst = gx + (size_t)m * G4 + n0 + tx * 8;
        float4 o0 = make_float4(acc[i][0] + bvals[0], acc[i][1] + bvals[1],
                                acc[i][2] + bvals[2], acc[i][3] + bvals[3]);
        float4 o1 = make_float4(acc[i][4] + bvals[4], acc[i][5] + bvals[5],
                                acc[i][6] + bvals[6], acc[i][7] + bvals[7]);
        *(float4*)(dst) = o0;
        *(float4*)(dst + 4) = o1;
    }
}

// ------ bidirectional LSTM, 4-CTA cluster, fp16 W resident in SMEM ---------
// grid 128, cluster (4,1,1). bx: rank=bx&3, cid=bx>>2, dir=cid&1, grp=cid>>1.
// Cluster = 4 batches perm[4*grp..+3]; rank owns gate cols [rank*256,+256),
// W slice (128 KB fp16) loaded to SMEM once. Thread t: col=t&255, pair g=t>>8
// -> computes cols' preacts for batches {2g, 2g+1}; pushes the pair as one
// 8B DSMEM store to all 4 CTAs' pre[s&1]; single cluster.sync; all CTAs
// redundantly compute activations (thread (g,j) owns c for batches 2g,2g+1).
// h kept in hI[k2][g] = (hA[2k2], hB[2k2], hA[2k2+1], hB[2k2+1]) float4 for
// warp-uniform broadcast reads in the matvec.
__global__ __launch_bounds__(512, 1) __cluster_dims__(4, 1, 1)
void lstm_kernel(const int* __restrict__ lens, float* __restrict__ feats)
{
    extern __shared__ float sm[];
    __half2* sW  = (__half2*)sm;           // [128 k2][256 cols]  128 KB
    float*   hI  = sm + 32768;             // [128 k2][2 g][4]      4 KB
    float*   pre = sm + 32768 + 1024;      // [2 buf][1024 col][4 b] 32 KB
    __shared__ int sB[4], sL[4];

    const int t = threadIdx.x;
    const unsigned int rank = ctarank();
    const int cid = blockIdx.x >> 2;
    const int dir = cid & 1;
    const int grp = cid >> 1;
    const __half2* __restrict__ Wp = dir ? g_WhB : g_WhF;
    const float*   __restrict__ gx = dir ? g_gx_b : g_gx_f;

    if (t < 4) { int b = g_perm[grp * 4 + t]; sB[t] = b; sL[t] = lens[b]; }
    for (int i = t; i < 32768; i += 512) {
        int k2 = i >> 8, c = i & 255;
        sW[i] = Wp[(size_t)k2 * G4 + (int)rank * 256 + c];
    }
    for (int i = t; i < 1024; i += 512) hI[i] = 0.0f;
    __syncthreads();

    const int col = t & 255, g = t >> 8;
    const int gcol = (int)rank * 256 + col;
    const int j = col;

    // remote pre addresses: pre[bf][gcol][2g] (8B-aligned pair)
    unsigned int pr[2][4];
#pragma unroll
    for (int bf = 0; bf < 2; bf++) {
        unsigned int loc = smem_u32(&pre[(bf * 1024 + gcol) * 4 + 2 * g]);
#pragma unroll
        for (int r = 0; r < 4; r++) pr[bf][r] = mapa_rank(loc, r);
    }

    const int bA = 2 * g, bB = 2 * g + 1;
    const int LA = sL[bA], LB = sL[bB], Lmax = sL[0];
    const size_t gbA = (size_t)sB[bA] * TT * G4 + gcol;
    const size_t gbB = (size_t)sB[bB] * TT * G4 + gcol;
    const bool wrA = (bA == (int)rank), wrB = (bB == (int)rank);
    const size_t fbA = (size_t)sB[bA] * TT * (2 * HH) + dir * HH + j;
    const size_t fbB = (size_t)sB[bB] * TT * (2 * HH) + dir * HH + j;
    float cA = 0.0f, cB = 0.0f;
    float* hw = hI + ((j >> 1) * 2 + g) * 4 + (j & 1) * 2;

    CLUSTER_SYNC();

    for (int s = 0; s < Lmax; s++) {
        const bool actA = s < LA, actB = s < LB;
        const int tA = actA ? (dir ? LA - 1 - s : s) : 0;
        const int tB = actB ? (dir ? LB - 1 - s : s) : 0;
        float gvA = gx[gbA + (size_t)tA * G4];     // prefetch, used after matvec
        float gvB = gx[gbB + (size_t)tB * G4];

        float aA = 0.0f, aB = 0.0f;
        const float4* __restrict__ hp = (const float4*)hI + g;
#pragma unroll 8
        for (int k2 = 0; k2 < 128; k2++) {
            float2 wf = __half22float2(sW[k2 * 256 + col]);
            float4 h4 = hp[k2 * 2];                // warp-uniform -> broadcast
            aA = fmaf(wf.x, h4.x, aA); aB = fmaf(wf.x, h4.y, aB);
            aA = fmaf(wf.y, h4.z, aA); aB = fmaf(wf.y, h4.w, aB);
        }
        const int bf = s & 1;
        float pA = aA + gvA, pB = aB + gvB;
        st_cluster2(pr[bf][0], pA, pB);
        st_cluster2(pr[bf][1], pA, pB);
        st_cluster2(pr[bf][2], pA, pB);
        st_cluster2(pr[bf][3], pA, pB);
        CLUSTER_SYNC();   // full 4-batch preacts visible everywhere

        {
            const float* pb = pre + bf * 4096 + 2 * g;
            float2 iv = *(const float2*)&pb[(0 * 256 + j) * 4];
            float2 fv = *(const float2*)&pb[(1 * 256 + j) * 4];
            float2 gg = *(const float2*)&pb[(2 * 256 + j) * 4];
            float2 ov = *(const float2*)&pb[(3 * 256 + j) * 4];
            if (actA) {
                cA = fmaf(sigf(fv.x), cA, sigf(iv.x) * tanhff(gg.x));
                float hv = sigf(ov.x) * tanhff(cA);
                hw[0] = hv;
                if (wrA) feats[fbA + (size_t)tA * (2 * HH)] = hv;
            }
            if (actB) {
                cB = fmaf(sigf(fv.y), cB, sigf(iv.y) * tanhff(gg.y));
                float hv = sigf(ov.y) * tanhff(cB);
                hw[1] = hv;
                if (wrB) feats[fbB + (size_t)tB * (2 * HH)] = hv;
            }
        }
        __syncthreads();   // hI updates visible to next matvec (intra-CTA)
    }
}

// ---------------- emissions: feats @ W_out^T + b_out ----------------------
__global__ void emis_kernel(const float* __restrict__ feats,
                            const float* __restrict__ Wout,
                            const float* __restrict__ bout)
{
    __shared__ float sW[KK][2 * HH];
    const int tid = threadIdx.x;
    for (int i = tid; i < KK * 2 * HH; i += 256)
        sW[i / (2 * HH)][i % (2 * HH)] = Wout[i];
    __syncthreads();

    const int warp = tid >> 5, lane = tid & 31;
    const int row = blockIdx.x * 8 + warp;
    const float* __restrict__ fr = feats + (size_t)row * (2 * HH);
    float acc[KK];
#pragma unroll
    for (int k = 0; k < KK; k++) acc[k] = 0.0f;
#pragma unroll 4
    for (int it = 0; it < 16; it++) {
        float x = fr[it * 32 + lane];
#pragma unroll
        for (int k = 0; k < KK; k++) acc[k] = fmaf(x, sW[k][it * 32 + lane], acc[k]);
    }
#pragma unroll
    for (int k = 0; k < KK; k++) {
        float v = acc[k];
#pragma unroll
        for (int off = 16; off; off >>= 1) v += __shfl_xor_sync(0xffffffffu, v, off);
        if (lane == 0) g_emis[(size_t)row * KK + k] = v + bout[k];
    }
}

// ---------------- CRF: alpha + numerator (warp0), viterbi + preds (warp1) --
__global__ void crf_kernel(const int* __restrict__ lens, const int* __restrict__ labels,
                           const float* __restrict__ start_t, const float* __restrict__ end_t,
                           const float* __restrict__ trans, float* __restrict__ preds_out)
{
    const int b = blockIdx.x;
    const int L = lens[b];
    const int tid = threadIdx.x, warp = tid >> 5, lane = tid & 31;
    const float* __restrict__ em = g_emis + (size_t)b * TT * KK;
    __shared__ unsigned char hist[TT][KK];

    const float NEG = -1e30f;
    const int j = lane;
    float tr[KK];
#pragma unroll
    for (int i = 0; i < KK; i++) tr[i] = (j < KK) ? trans[i * KK + j] : 0.0f;

    if (warp == 0) {
        float score = (j < KK) ? (start_t[j] + em[j]) : NEG;
        for (int t = 1; t < L; t++) {
            float v[KK], mx = NEG;
#pragma unroll
            for (int i = 0; i < KK; i++) {
                v[i] = __shfl_sync(0xffffffffu, score, i) + tr[i];
                mx = fmaxf(mx, v[i]);
            }
            float sum = 0.0f;
#pragma unroll
            for (int i = 0; i < KK; i++) sum += __expf(v[i] - mx);
            float e = (j < KK) ? em[t * KK + j] : 0.0f;
            float nxt = mx + __logf(sum) + e;
            if (j < KK) score = nxt;
        }
        float z = (j < KK) ? (score + end_t[j]) : NEG;
        float mz = z;
#pragma unroll
        for (int off = 16; off; off >>= 1) mz = fmaxf(mz, __shfl_xor_sync(0xffffffffu, mz, off));
        float se = (j < KK) ? __expf(z - mz) : 0.0f;
#pragma unroll
        for (int off = 16; off; off >>= 1) se += __shfl_xor_sync(0xffffffffu, se, off);
        float denom = mz + __logf(se);

        const int* __restrict__ lab = labels + b * TT;
        float acc = 0.0f;
        for (int t = 1 + lane; t < L; t += 32) {
            int yp = lab[t - 1], y = lab[t];
            acc += trans[yp * KK + y] + em[t * KK + y];
        }
#pragma unroll
        for (int off = 16; off; off >>= 1) acc += __shfl_xor_sync(0xffffffffu, acc, off);
        if (lane == 0) {
            int y0 = lab[0], yl = lab[L - 1];
            float num = acc + start_t[y0] + em[y0] + end_t[yl];
            g_loss[b] = num - denom;
        }
    } else {
        float score = (j < KK) ? (start_t[j] + em[j]) : NEG;
        for (int t = 1; t < L; t++) {
            float best = NEG; int barg = 0;
#pragma unroll
            for (int i = 0; i < KK; i++) {
                float v = __shfl_sync(0xffffffffu, score, i) + tr[i];
                if (v > best) { best = v; barg = i; }
            }
            if (j < KK) {
                hist[t - 1][j] = (unsigned char)barg;
                score = best + em[t * KK + j];
            }
        }
        float z = (j < KK) ? (score + end_t[j]) : NEG;
        int idx = j;
#pragma unroll
        for (int off = 16; off; off >>= 1) {
            float oz = __shfl_xor_sync(0xffffffffu, z, off);
            int   oi = __shfl_xor_sync(0xffffffffu, idx, off);
            if (oz > z || (oz == z && oi < idx)) { z = oz; idx = oi; }
        }
        int best_last = __shfl_sync(0xffffffffu, idx, 0);

        float* __restrict__ po = preds_out + (size_t)b * TT;
        for (int t = L + lane; t < TT; t += 32) po[t] = 0.0f;
        if (lane == 0) {
            int cur = best_last;
            po[L - 1] = (float)cur;
            for (int t = L - 2; t >= 0; t--) { cur = hist[t][cur]; po[t] = (float)cur; }
        }
    }
}

// ---------------- deterministic loss reduction ----------------------------
__global__ void finalize_kernel(float* __restrict__ out) {
    if (threadIdx.x == 0) {
        float s = 0.0f;
        for (int i = 0; i < BB; i++) s += g_loss[i];
        out[0] = -s / (float)BB;
    }
}

// ---------------- launch ---------------------------------------------------
extern "C" void kernel_launch(void* const* d_in, const int* in_sizes, int n_in,
                              void* d_out, int out_size) {
    const int*   wi    = (const int*)d_in[0];
    const int*   lens  = (const int*)d_in[1];
    const int*   lab   = (const int*)d_in[2];
    const float* wv    = (const float*)d_in[3];
    const float* Wihf  = (const float*)d_in[4];
    const float* Whhf  = (const float*)d_in[5];
    const float* bf    = (const float*)d_in[6];
    const float* Wihb  = (const float*)d_in[7];
    const float* Whhb  = (const float*)d_in[8];
    const float* bb    = (const float*)d_in[9];
    const float* Wout  = (const float*)d_in[10];
    const float* bout  = (const float*)d_in[11];
    const float* st    = (const float*)d_in[12];
    const float* en    = (const float*)d_in[13];
    const float* tr    = (const float*)d_in[14];

    float* out       = (float*)d_out;
    float* preds_out = out + 1;
    float* feats     = out + 1 + BB * TT;

    const int lstm_smem = (32768 + 1024 + 8192) * 4;   // 167936 B
    cudaFuncSetAttribute(lstm_kernel,
                         cudaFuncAttributeMaxDynamicSharedMemorySize, lstm_smem);

    const int nfeat = MTOT * 2 * HH;
    zero_kernel<<<(nfeat + 255) / 256, 256>>>(feats, nfeat);
    prep_kernel<<<dim3(32, 8, 2), 256>>>(Whhf, Whhb);
    sort_kernel<<<1, BB>>>(lens);
    gemm_kernel<<<dim3(G4 / 128, MTOT / 128, 2), 256>>>(wi, lens, wv, Wihf, bf, Wihb, bb);
    lstm_kernel<<<128, 512, lstm_smem>>>(lens, feats);
    emis_kernel<<<MTOT / 8, 256>>>(feats, Wout, bout);
    crf_kernel<<<BB, 64>>>(lens, lab, st, en, tr, preds_out);
    finalize_kernel<<<1, 32>>>(out);
}

// round 15
// speedup vs baseline: 1.8375x; 1.0053x over previous
#include <cuda_runtime.h>
#include <cuda_fp16.h>
#include <cstdint>
#include <math.h>

#define BB 64
#define TT 512
#define EE 256
#define HH 256
#define KK 9
#define G4 1024              // 4*H
#define MTOT (BB*TT)         // 32768

// ---------------- scratch (device globals; no allocations allowed) ----------
__device__ float   g_gx_f[(size_t)MTOT * G4];  // forward input-gate preacts (+bias)
__device__ float   g_gx_b[(size_t)MTOT * G4];  // backward input-gate preacts (+bias)
__device__ __half2 g_WhF[(size_t)128 * G4];    // W_hh_f fp16, [k/2][1024] (lo=even k)
__device__ __half2 g_WhB[(size_t)128 * G4];    // W_hh_b fp16
__device__ int     g_perm[BB];                 // batches sorted by length (desc)
__device__ float   g_emis[(size_t)MTOT * KK];  // emissions
__device__ float   g_loss[BB];                 // per-batch (num - denom)

__device__ __forceinline__ float sigf(float x)  { return 1.0f / (1.0f + __expf(-x)); }
__device__ __forceinline__ float tanhff(float x){ return 1.0f - 2.0f / (__expf(2.0f * x) + 1.0f); }

__device__ __forceinline__ unsigned int smem_u32(const void* p) {
    unsigned int a;
    asm("{ .reg .u64 t; cvta.to.shared.u64 t, %1; cvt.u32.u64 %0, t; }" : "=r"(a) : "l"(p));
    return a;
}
__device__ __forceinline__ unsigned int mapa_rank(unsigned int a, unsigned int r) {
    unsigned int d;
    asm("mapa.shared::cluster.u32 %0, %1, %2;" : "=r"(d) : "r"(a), "r"(r));
    return d;
}
__device__ __forceinline__ void st_cluster2(unsigned int a, float x, float y) {
    asm volatile("st.shared::cluster.v2.f32 [%0], {%1, %2};"
                 :: "r"(a), "f"(x), "f"(y) : "memory");
}
__device__ __forceinline__ unsigned int ctarank() {
    unsigned int r; asm("mov.u32 %0, %%cluster_ctarank;" : "=r"(r)); return r;
}
#define CLUSTER_SYNC() do { \
    asm volatile("barrier.cluster.arrive.aligned;" ::: "memory"); \
    asm volatile("barrier.cluster.wait.aligned;"   ::: "memory"); \
} while (0)

// ---------------- zero feats region --------------------------------------
__global__ void zero_kernel(float* __restrict__ p, int n) {
    int i = blockIdx.x * blockDim.x + threadIdx.x;
    if (i < n) p[i] = 0.0f;
}

// ---- transpose+convert W_hh (1024x256 fp32 -> [k/2][1024] half2), both dirs
__global__ void prep_kernel(const float* __restrict__ Whh_f,
                            const float* __restrict__ Whh_b)
{
    __shared__ float tile[32][33];                 // [n][k]
    const float* __restrict__ W  = blockIdx.z ? Whh_b : Whh_f;
    __half2* __restrict__     Wh = blockIdx.z ? g_WhB : g_WhF;
    const int n0 = blockIdx.x * 32;   // gate row 0..1023
    const int k0 = blockIdx.y * 32;   // k 0..255
    const int tx = threadIdx.x & 31, ty = threadIdx.x >> 5;  // 32x8
#pragma unroll
    for (int i = 0; i < 32; i += 8)
        tile[ty + i][tx] = W[(size_t)(n0 + ty + i) * HH + k0 + tx];
    __syncthreads();
#pragma unroll
    for (int i = 0; i < 16; i += 8) {
        int k2 = ty + i;              // 0..15 local
        __half2 v = __floats2half2_rn(tile[tx][2 * k2], tile[tx][2 * k2 + 1]);
        Wh[(size_t)(k0 / 2 + k2) * G4 + n0 + tx] = v;
    }
}

// ---------------- sort batches by length (descending), odd-even ------------
__global__ void sort_kernel(const int* __restrict__ lens) {
    __shared__ int keys[BB];
    const int t = threadIdx.x;
    keys[t] = (lens[t] << 8) | t;
    for (int phase = 0; phase < BB; phase++) {
        __syncthreads();
        if ((t & 1) == (phase & 1) && t + 1 < BB) {
            int a = keys[t], b = keys[t + 1];
            if (a < b) { keys[t] = b; keys[t + 1] = a; }
        }
    }
    __syncthreads();
    g_perm[t] = keys[t] & 255;
}

// ---------------- fused embedding-gather + input GEMM ---------------------
__global__ __launch_bounds__(256, 2)
void gemm_kernel(const int* __restrict__ word_inputs,
                 const int* __restrict__ lens,
                 const float* __restrict__ word_vec,
                 const float* __restrict__ Wf, const float* __restrict__ bf,
                 const float* __restrict__ Wb, const float* __restrict__ bb)
{
    const int dir = blockIdx.z;
    const float* __restrict__ Wih  = dir ? Wb : Wf;
    const float* __restrict__ bias = dir ? bb : bf;
    float* __restrict__ gx = dir ? g_gx_b : g_gx_f;

    const int m0 = blockIdx.y * 128;
    const int n0 = blockIdx.x * 128;
    const int bidx = m0 >> 9;
    const int t0   = m0 & 511;
    if (t0 >= lens[bidx]) return;

    __shared__ float As[8][128];
    __shared__ float Bs[8][128];
    __shared__ int   sIdx[128];

    const int tid = threadIdx.x;
    if (tid < 128) sIdx[tid] = word_inputs[m0 + tid];
    __syncthreads();

    const int lr = tid >> 1;
    const int kq = (tid & 1) * 4;
    const int ty = tid >> 4, tx = tid & 15;

    const float* __restrict__ arow = word_vec + (size_t)sIdx[lr] * EE;
    const float* __restrict__ brow = Wih + (size_t)(n0 + lr) * EE;

    float acc[8][8];
#pragma unroll
    for (int i = 0; i < 8; i++)
#pragma unroll
        for (int j = 0; j < 8; j++) acc[i][j] = 0.0f;

    for (int k0 = 0; k0 < EE; k0 += 8) {
        float4 av = *(const float4*)(arow + k0 + kq);
        float4 bv = *(const float4*)(brow + k0 + kq);
        __syncthreads();
        As[kq + 0][lr] = av.x; As[kq + 1][lr] = av.y;
        As[kq + 2][lr] = av.z; As[kq + 3][lr] = av.w;
        Bs[kq + 0][lr] = bv.x; Bs[kq + 1][lr] = bv.y;
        Bs[kq + 2][lr] = bv.z; Bs[kq + 3][lr] = bv.w;
        __syncthreads();
#pragma unroll
        for (int kk = 0; kk < 8; kk++) {
            float4 a0 = *(const float4*)&As[kk][ty * 8];
            float4 a1 = *(const float4*)&As[kk][ty * 8 + 4];
            float4 b0 = *(const float4*)&Bs[kk][tx * 8];
            float4 b1 = *(const float4*)&Bs[kk][tx * 8 + 4];
            float a[8] = {a0.x, a0.y, a0.z, a0.w, a1.x, a1.y, a1.z, a1.w};
            float b[8] = {b0.x, b0.y, b0.z, b0.w, b1.x, b1.y, b1.z, b1.w};
#pragma unroll
            for (int i = 0; i < 8; i++)
#pragma unroll
                for (int j = 0; j < 8; j++)
                    acc[i][j] = fmaf(a[i], b[j], acc[i][j]);
        }
    }

    const float* bsrc = bias + n0 + tx * 8;
    float4 bb0 = *(const float4*)(bsrc);
    float4 bb1 = *(const float4*)(bsrc + 4);
    float bvals[8] = {bb0.x, bb0.y, bb0.z, bb0.w, bb1.x, bb1.y, bb1.z, bb1.w};
#pragma unroll
    for (int i = 0; i < 8; i++) {
        int m = m0 + ty * 8 + i;
        float* dst = gx + (size_t)m * G4 + n0 + tx * 8;
        float4 o0 = make_float4(acc[i][0] + bvals[0], acc[i][1] + bvals[1],
                                acc[i][2] + bvals[2], acc[i][3] + bvals[3]);
        float4 o1 = make_float4(acc[i][4] + bvals[4], acc[i][5] + bvals[5],
                                acc[i][6] + bvals[6], acc[i][7] + bvals[7]);
        *(float4*)(dst) = o0;
        *(float4*)(dst + 4) = o1;
    }
}

// ------ bidirectional LSTM, 4-CTA cluster, fp16 W resident in SMEM ---------
// grid 128, cluster (4,1,1). bx: rank=bx&3, cid=bx>>2, dir=cid&1, grp=cid>>1.
// Cluster = 4 batches perm[4*grp..+3]; rank owns gate cols [rank*256,+256),
// W slice (128 KB fp16) loaded to SMEM once. Thread t: col=t&255, pair g=t>>8
// -> computes cols' preacts for batches {2g, 2g+1}; pushes the pair as one
// 8B DSMEM store to all 4 CTAs' pre[s&1]; single cluster.sync; all CTAs
// redundantly compute activations (thread (g,j) owns c for batches 2g,2g+1).
// h kept in hI[k2][g] = (hA[2k2], hB[2k2], hA[2k2+1], hB[2k2+1]) float4 for
// warp-uniform broadcast reads in the matvec.
__global__ __launch_bounds__(512, 1) __cluster_dims__(4, 1, 1)
void lstm_kernel(const int* __restrict__ lens, float* __restrict__ feats)
{
    extern __shared__ float sm[];
    __half2* sW  = (__half2*)sm;           // [128 k2][256 cols]  128 KB
    float*   hI  = sm + 32768;             // [128 k2][2 g][4]      4 KB
    float*   pre = sm + 32768 + 1024;      // [2 buf][1024 col][4 b] 32 KB
    __shared__ int sB[4], sL[4];

    const int t = threadIdx.x;
    const unsigned int rank = ctarank();
    const int cid = blockIdx.x >> 2;
    const int dir = cid & 1;
    const int grp = cid >> 1;
    const __half2* __restrict__ Wp = dir ? g_WhB : g_WhF;
    const float*   __restrict__ gx = dir ? g_gx_b : g_gx_f;

    if (t < 4) { int b = g_perm[grp * 4 + t]; sB[t] = b; sL[t] = lens[b]; }
    for (int i = t; i < 32768; i += 512) {
        int k2 = i >> 8, c = i & 255;
        sW[i] = Wp[(size_t)k2 * G4 + (int)rank * 256 + c];
    }
    for (int i = t; i < 1024; i += 512) hI[i] = 0.0f;
    __syncthreads();

    const int col = t & 255, g = t >> 8;
    const int gcol = (int)rank * 256 + col;
    const int j = col;

    // remote pre addresses: pre[bf][gcol][2g] (8B-aligned pair)
    unsigned int pr[2][4];
#pragma unroll
    for (int bf = 0; bf < 2; bf++) {
        unsigned int loc = smem_u32(&pre[(bf * 1024 + gcol) * 4 + 2 * g]);
#pragma unroll
        for (int r = 0; r < 4; r++) pr[bf][r] = mapa_rank(loc, r);
    }

    const int bA = 2 * g, bB = 2 * g + 1;
    const int LA = sL[bA], LB = sL[bB], Lmax = sL[0];
    const size_t gbA = (size_t)sB[bA] * TT * G4 + gcol;
    const size_t gbB = (size_t)sB[bB] * TT * G4 + gcol;
    const bool wrA = (bA == (int)rank), wrB = (bB == (int)rank);
    const size_t fbA = (size_t)sB[bA] * TT * (2 * HH) + dir * HH + j;
    const size_t fbB = (size_t)sB[bB] * TT * (2 * HH) + dir * HH + j;
    float cA = 0.0f, cB = 0.0f;
    float* hw = hI + ((j >> 1) * 2 + g) * 4 + (j & 1) * 2;

    CLUSTER_SYNC();

    for (int s = 0; s < Lmax; s++) {
        const bool actA = s < LA, actB = s < LB;
        const int tA = actA ? (dir ? LA - 1 - s : s) : 0;
        const int tB = actB ? (dir ? LB - 1 - s : s) : 0;
        float gvA = gx[gbA + (size_t)tA * G4];     // prefetch, used after matvec
        float gvB = gx[gbB + (size_t)tB * G4];

        float aA = 0.0f, aB = 0.0f;
        const float4* __restrict__ hp = (const float4*)hI + g;
#pragma unroll 8
        for (int k2 = 0; k2 < 128; k2++) {
            float2 wf = __half22float2(sW[k2 * 256 + col]);
            float4 h4 = hp[k2 * 2];                // warp-uniform -> broadcast
            aA = fmaf(wf.x, h4.x, aA); aB = fmaf(wf.x, h4.y, aB);
            aA = fmaf(wf.y, h4.z, aA); aB = fmaf(wf.y, h4.w, aB);
        }
        const int bf = s & 1;
        float pA = aA + gvA, pB = aB + gvB;
        st_cluster2(pr[bf][0], pA, pB);
        st_cluster2(pr[bf][1], pA, pB);
        st_cluster2(pr[bf][2], pA, pB);
        st_cluster2(pr[bf][3], pA, pB);
        CLUSTER_SYNC();   // full 4-batch preacts visible everywhere

        {
            const float* pb = pre + bf * 4096 + 2 * g;
            float2 iv = *(const float2*)&pb[(0 * 256 + j) * 4];
            float2 fv = *(const float2*)&pb[(1 * 256 + j) * 4];
            float2 gg = *(const float2*)&pb[(2 * 256 + j) * 4];
            float2 ov = *(const float2*)&pb[(3 * 256 + j) * 4];
            if (actA) {
                cA = fmaf(sigf(fv.x), cA, sigf(iv.x) * tanhff(gg.x));
                float hv = sigf(ov.x) * tanhff(cA);
                hw[0] = hv;
                if (wrA) feats[fbA + (size_t)tA * (2 * HH)] = hv;
            }
            if (actB) {
                cB = fmaf(sigf(fv.y), cB, sigf(iv.y) * tanhff(gg.y));
                float hv = sigf(ov.y) * tanhff(cB);
                hw[1] = hv;
                if (wrB) feats[fbB + (size_t)tB * (2 * HH)] = hv;
            }
        }
        __syncthreads();   // hI updates visible to next matvec (intra-CTA)
    }
}

// ---------------- emissions: feats @ W_out^T + b_out ----------------------
__global__ void emis_kernel(const float* __restrict__ feats,
                            const float* __restrict__ Wout,
                            const float* __restrict__ bout)
{
    __shared__ float sW[KK][2 * HH];
    const int tid = threadIdx.x;
    for (int i = tid; i < KK * 2 * HH; i += 256)
        sW[i / (2 * HH)][i % (2 * HH)] = Wout[i];
    __syncthreads();

    const int warp = tid >> 5, lane = tid & 31;
    const int row = blockIdx.x * 8 + warp;
    const float* __restrict__ fr = feats + (size_t)row * (2 * HH);
    float acc[KK];
#pragma unroll
    for (int k = 0; k < KK; k++) acc[k] = 0.0f;
#pragma unroll 4
    for (int it = 0; it < 16; it++) {
        float x = fr[it * 32 + lane];
#pragma unroll
        for (int k = 0; k < KK; k++) acc[k] = fmaf(x, sW[k][it * 32 + lane], acc[k]);
    }
#pragma unroll
    for (int k = 0; k < KK; k++) {
        float v = acc[k];
#pragma unroll
        for (int off = 16; off; off >>= 1) v += __shfl_xor_sync(0xffffffffu, v, off);
        if (lane == 0) g_emis[(size_t)row * KK + k] = v + bout[k];
    }
}

// ---------------- CRF: alpha + numerator (warp0), viterbi + preds (warp1) --
__global__ void crf_kernel(const int* __restrict__ lens, const int* __restrict__ labels,
                           const float* __restrict__ start_t, const float* __restrict__ end_t,
                           const float* __restrict__ trans, float* __restrict__ preds_out)
{
    const int b = blockIdx.x;
    const int L = lens[b];
    const int tid = threadIdx.x, warp = tid >> 5, lane = tid & 31;
    const float* __restrict__ em = g_emis + (size_t)b * TT * KK;
    __shared__ unsigned char hist[TT][KK];

    const float NEG = -1e30f;
    const int j = lane;
    float tr[KK];
#pragma unroll
    for (int i = 0; i < KK; i++) tr[i] = (j < KK) ? trans[i * KK + j] : 0.0f;

    if (warp == 0) {
        float score = (j < KK) ? (start_t[j] + em[j]) : NEG;
        for (int t = 1; t < L; t++) {
            float v[KK], mx = NEG;
#pragma unroll
            for (int i = 0; i < KK; i++) {
                v[i] = __shfl_sync(0xffffffffu, score, i) + tr[i];
                mx = fmaxf(mx, v[i]);
            }
            float sum = 0.0f;
#pragma unroll
            for (int i = 0; i < KK; i++) sum += __expf(v[i] - mx);
            float e = (j < KK) ? em[t * KK + j] : 0.0f;
            float nxt = mx + __logf(sum) + e;
            if (j < KK) score = nxt;
        }
        float z = (j < KK) ? (score + end_t[j]) : NEG;
        float mz = z;
#pragma unroll
        for (int off = 16; off; off >>= 1) mz = fmaxf(mz, __shfl_xor_sync(0xffffffffu, mz, off));
        float se = (j < KK) ? __expf(z - mz) : 0.0f;
#pragma unroll
        for (int off = 16; off; off >>= 1) se += __shfl_xor_sync(0xffffffffu, se, off);
        float denom = mz + __logf(se);

        const int* __restrict__ lab = labels + b * TT;
        float acc = 0.0f;
        for (int t = 1 + lane; t < L; t += 32) {
            int yp = lab[t - 1], y = lab[t];
            acc += trans[yp * KK + y] + em[t * KK + y];
        }
#pragma unroll
        for (int off = 16; off; off >>= 1) acc += __shfl_xor_sync(0xffffffffu, acc, off);
        if (lane == 0) {
            int y0 = lab[0], yl = lab[L - 1];
            float num = acc + start_t[y0] + em[y0] + end_t[yl];
            g_loss[b] = num - denom;
        }
    } else {
        float score = (j < KK) ? (start_t[j] + em[j]) : NEG;
        for (int t = 1; t < L; t++) {
            float best = NEG; int barg = 0;
#pragma unroll
            for (int i = 0; i < KK; i++) {
                float v = __shfl_sync(0xffffffffu, score, i) + tr[i];
                if (v > best) { best = v; barg = i; }
            }
            if (j < KK) {
                hist[t - 1][j] = (unsigned char)barg;
                score = best + em[t * KK + j];
            }
        }
        float z = (j < KK) ? (score + end_t[j]) : NEG;
        int idx = j;
#pragma unroll
        for (int off = 16; off; off >>= 1) {
            float oz = __shfl_xor_sync(0xffffffffu, z, off);
            int   oi = __shfl_xor_sync(0xffffffffu, idx, off);
            if (oz > z || (oz == z && oi < idx)) { z = oz; idx = oi; }
        }
        int best_last = __shfl_sync(0xffffffffu, idx, 0);

        float* __restrict__ po = preds_out + (size_t)b * TT;
        for (int t = L + lane; t < TT; t += 32) po[t] = 0.0f;
        if (lane == 0) {
            int cur = best_last;
            po[L - 1] = (float)cur;
            for (int t = L - 2; t >= 0; t--) { cur = hist[t][cur]; po[t] = (float)cur; }
        }
    }
}

// ---------------- deterministic loss reduction ----------------------------
__global__ void finalize_kernel(float* __restrict__ out) {
    if (threadIdx.x == 0) {
        float s = 0.0f;
        for (int i = 0; i < BB; i++) s += g_loss[i];
        out[0] = -s / (float)BB;
    }
}

// ---------------- launch ---------------------------------------------------
extern "C" void kernel_launch(void* const* d_in, const int* in_sizes, int n_in,
                              void* d_out, int out_size) {
    const int*   wi    = (const int*)d_in[0];
    const int*   lens  = (const int*)d_in[1];
    const int*   lab   = (const int*)d_in[2];
    const float* wv    = (const float*)d_in[3];
    const float* Wihf  = (const float*)d_in[4];
    const float* Whhf  = (const float*)d_in[5];
    const float* bf    = (const float*)d_in[6];
    const float* Wihb  = (const float*)d_in[7];
    const float* Whhb  = (const float*)d_in[8];
    const float* bb    = (const float*)d_in[9];
    const float* Wout  = (const float*)d_in[10];
    const float* bout  = (const float*)d_in[11];
    const float* st    = (const float*)d_in[12];
    const float* en    = (const float*)d_in[13];
    const float* tr    = (const float*)d_in[14];

    float* out       = (float*)d_out;
    float* preds_out = out + 1;
    float* feats     = out + 1 + BB * TT;

    const int lstm_smem = (32768 + 1024 + 8192) * 4;   // 167936 B
    cudaFuncSetAttribute(lstm_kernel,
                         cudaFuncAttributeMaxDynamicSharedMemorySize, lstm_smem);

    const int nfeat = MTOT * 2 * HH;
    zero_kernel<<<(nfeat + 255) / 256, 256>>>(feats, nfeat);
    prep_kernel<<<dim3(32, 8, 2), 256>>>(Whhf, Whhb);
    sort_kernel<<<1, BB>>>(lens);
    gemm_kernel<<<dim3(G4 / 128, MTOT / 128, 2), 256>>>(wi, lens, wv, Wihf, bf, Wihb, bb);
    lstm_kernel<<<128, 512, lstm_smem>>>(lens, feats);
    emis_kernel<<<MTOT / 8, 256>>>(feats, Wout, bout);
    crf_kernel<<<BB, 64>>>(lens, lab, st, en, tr, preds_out);
    finalize_kernel<<<1, 32>>>(out);
}